// round 1
// baseline (speedup 1.0000x reference)
#include <cuda_runtime.h>

// VectorQuantizer: latents [32,64,64,64] (B,D,H,W), emb [512,64].
// N = 32*64*64 = 131072 pixels, D=64, K=512.
// out[0 .. N*D) = straight-through quantized tensor in (B,D,H,W) layout
// out[out_size-1] = vq_loss = 1.25 * mean((q - lat)^2)

#define VQ_K     512
#define VQ_D     64
#define VQ_HW    4096          // H*W
#define VQ_NPIX  131072        // B*H*W
#define VQ_ND    8388608       // NPIX * D
#define THREADS  256
#define SMEM_BYTES (VQ_K * VQ_D * 4 + VQ_K * 4)   // codes + sume2 = 133120 B

__device__ float  g_sume2[VQ_K];
__device__ double g_loss_acc;

// ---- setup: per-code ||e||^2 (sequential fp32, mul+add, no fma) and zero the
// loss accumulator (graph replays must be idempotent).
__global__ void vq_setup_kernel(const float* __restrict__ emb) {
    int k = threadIdx.x;
    if (k == 0) g_loss_acc = 0.0;
    if (k < VQ_K) {
        const float* e = emb + k * VQ_D;
        float acc = 0.0f;
#pragma unroll
        for (int d = 0; d < VQ_D; d++)
            acc = __fadd_rn(acc, __fmul_rn(e[d], e[d]));
        g_sume2[k] = acc;
    }
}

// ---- main: one pixel per thread, full codebook staged in smem.
__global__ void __launch_bounds__(THREADS, 1)
vq_main_kernel(const float* __restrict__ lat,
               const float* __restrict__ emb,
               float* __restrict__ out) {
    extern __shared__ float sm[];                 // [K*D] codes, then [K] sume2
    float* sm_codes = sm;
    float* sm_s     = sm + VQ_K * VQ_D;

    // stage codebook (row-major [K][D], same layout as gmem) as float4
    {
        const float4* src = (const float4*)emb;
        float4* dst = (float4*)sm_codes;
        for (int i = threadIdx.x; i < VQ_K * VQ_D / 4; i += THREADS)
            dst[i] = src[i];
        for (int i = threadIdx.x; i < VQ_K; i += THREADS)
            sm_s[i] = g_sume2[i];
    }
    __syncthreads();

    const int n    = blockIdx.x * THREADS + threadIdx.x;   // pixel id
    const int b    = n >> 12;                              // / 4096
    const int s    = n & 4095;
    const long base = (long)b * (VQ_D * VQ_HW) + s;

    // load this pixel's D components (stride HW, coalesced across threads)
    float x[VQ_D];
#pragma unroll
    for (int d = 0; d < VQ_D; d++)
        x[d] = lat[base + (long)d * VQ_HW];

    // ||x||^2, sequential mul+add (emulating jnp.sum(flat*flat, axis=1))
    float a = 0.0f;
#pragma unroll
    for (int d = 0; d < VQ_D; d++)
        a = __fadd_rn(a, __fmul_rn(x[d], x[d]));

    // argmin over codes: dist = fl( fl(a + ||e||^2) - 2*dot )
    float best = 3.4e38f;
    int   bi   = 0;
    for (int k = 0; k < VQ_K; k++) {
        const float4* e4 = (const float4*)(sm_codes + k * VQ_D);
        float dot = 0.0f;
#pragma unroll
        for (int d4 = 0; d4 < VQ_D / 4; d4++) {
            float4 ev = e4[d4];
            dot = __fmaf_rn(x[d4 * 4 + 0], ev.x, dot);
            dot = __fmaf_rn(x[d4 * 4 + 1], ev.y, dot);
            dot = __fmaf_rn(x[d4 * 4 + 2], ev.z, dot);
            dot = __fmaf_rn(x[d4 * 4 + 3], ev.w, dot);
        }
        float t    = __fadd_rn(a, sm_s[k]);
        float dist = __fmaf_rn(-2.0f, dot, t);   // == fl(t - fl(2*dot)), 2*dot exact
        if (dist < best) { best = dist; bi = k; }
    }

    // gather winning code, write straight-through output, accumulate loss
    const float* e = sm_codes + bi * VQ_D;
    double lacc = 0.0;
#pragma unroll
    for (int d = 0; d < VQ_D; d++) {
        float qd = e[d];
        float xd = x[d];
        float dm = __fsub_rn(qd, xd);            // q - lat
        out[base + (long)d * VQ_HW] = __fadd_rn(xd, dm);   // lat + (q - lat)
        float sq = __fmul_rn(dm, dm);
        lacc += (double)sq;
    }

    // warp-reduce the double partial, one atomic per warp
#pragma unroll
    for (int off = 16; off > 0; off >>= 1)
        lacc += __shfl_down_sync(0xFFFFFFFFu, lacc, off);
    if ((threadIdx.x & 31) == 0)
        atomicAdd(&g_loss_acc, lacc);
}

// ---- finalize: vq_loss = fl( fl(m*0.25) + m ), m = mean((q-lat)^2)
__global__ void vq_finalize_kernel(float* __restrict__ out, int out_size) {
    double mean = g_loss_acc / (double)VQ_ND;
    float m = (float)mean;
    out[out_size - 1] = __fadd_rn(__fmul_rn(m, 0.25f), m);
}

extern "C" void kernel_launch(void* const* d_in, const int* in_sizes, int n_in,
                              void* d_out, int out_size) {
    const float* lat = (const float*)d_in[0];
    const float* emb = (const float*)d_in[1];
    float* out = (float*)d_out;

    static bool attr_set = false;
    if (!attr_set) {
        cudaFuncSetAttribute(vq_main_kernel,
                             cudaFuncAttributeMaxDynamicSharedMemorySize,
                             SMEM_BYTES);
        attr_set = true;
    }

    vq_setup_kernel<<<1, VQ_K>>>(emb);
    vq_main_kernel<<<VQ_NPIX / THREADS, THREADS, SMEM_BYTES>>>(lat, emb, out);
    vq_finalize_kernel<<<1, 1>>>(out, out_size);
}

// round 2
// speedup vs baseline: 1.1710x; 1.1710x over previous
#include <cuda_runtime.h>

// VectorQuantizer: latents [32,64,64,64] (B,D,H,W), emb [512,64].
// N = 131072 pixels, D=64, K=512.
// out[0..N*D) = straight-through quantized tensor (== q) in (B,D,H,W) layout
// out[out_size-1] = vq_loss = 1.25 * mean((q - lat)^2)
//
// Strategy: packed fp32x2 FMA (SASS FFMA2, 2x fp32 throughput). Codebook is
// transposed to [D][K] in smem so LDS.128 yields two packed {e_k, e_k1} pairs
// directly in 64-bit register pairs. Each 32-bit lane of fma.rn.f32x2 rounds
// identically to scalar __fmaf_rn, so per-code dot chains stay bit-exact.

#define VQ_K     512
#define VQ_D     64
#define VQ_HW    4096
#define VQ_NPIX  131072
#define VQ_ND    8388608
#define THREADS  256
#define SMEM_BYTES (VQ_K * VQ_D * 4 + VQ_K * 4)   // 133120 B

__device__ float  g_embT[VQ_D * VQ_K];   // transposed codebook [d][k]
__device__ float  g_sume2[VQ_K];
__device__ double g_loss_acc;

#define FMA2(dst, a, b, c) \
    asm("fma.rn.f32x2 %0, %1, %2, %3;" : "=l"(dst) : "l"(a), "l"(b), "l"(c))
#define PACK2(dst, f) \
    asm("mov.b64 %0, {%1, %1};" : "=l"(dst) : "r"(__float_as_uint(f)))
#define UNPACK2(lo, hi, v) \
    asm("mov.b64 {%0, %1}, %2;" : "=r"(lo), "=r"(hi) : "l"(v))

// ---- setup: transpose codebook to [D][K], per-code ||e||^2 (sequential fp32),
// zero loss accumulator (graph replays must be idempotent).
__global__ void vq_setup_kernel(const float* __restrict__ emb) {
    int k = threadIdx.x;               // 512 threads, one per code
    if (k == 0) g_loss_acc = 0.0;
    const float* e = emb + k * VQ_D;
    float acc = 0.0f;
#pragma unroll
    for (int d = 0; d < VQ_D; d++) {
        float v = e[d];
        acc = __fadd_rn(acc, __fmul_rn(v, v));
        g_embT[d * VQ_K + k] = v;      // coalesced across threads per d
    }
    g_sume2[k] = acc;
}

// ---- main: one pixel per thread, transposed codebook in smem, FFMA2 dots.
__global__ void __launch_bounds__(THREADS)
vq_main_kernel(const float* __restrict__ lat,
               float* __restrict__ out) {
    extern __shared__ float sm[];               // [D*K] transposed codes, [K] sume2
    float* smT  = sm;
    float* sm_s = sm + VQ_D * VQ_K;

    // stage transposed codebook + sume2 (coalesced float4 copy from global)
    {
        const float4* src = (const float4*)g_embT;
        float4* dst = (float4*)smT;
        for (int i = threadIdx.x; i < VQ_D * VQ_K / 4; i += THREADS)
            dst[i] = src[i];
        const float4* ssrc = (const float4*)g_sume2;
        float4* sdst = (float4*)sm_s;
        for (int i = threadIdx.x; i < VQ_K / 4; i += THREADS)
            sdst[i] = ssrc[i];
    }
    __syncthreads();

    const int n = blockIdx.x * THREADS + threadIdx.x;    // pixel id
    const int b = n >> 12;
    const int s = n & 4095;
    const long base = (long)b * (VQ_D * VQ_HW) + s;

    // load pixel components (coalesced), sequential ||x||^2, pack {x,x}
    unsigned long long xp[VQ_D];
    float a = 0.0f;
#pragma unroll
    for (int d = 0; d < VQ_D; d++) {
        float xd = lat[base + (long)d * VQ_HW];
        a = __fadd_rn(a, __fmul_rn(xd, xd));
        PACK2(xp[d], xd);
    }

    float best = 3.4e38f;
    int   bi   = 0;

    // 8 codes per outer iteration: 2x LDS.128 + 4x FFMA2 per d
    for (int k0 = 0; k0 < VQ_K; k0 += 8) {
        unsigned long long dA = 0ull, dB = 0ull, dC = 0ull, dD = 0ull;
#pragma unroll
        for (int d = 0; d < VQ_D; d++) {
            const float* row = smT + d * VQ_K + k0;
            ulonglong2 eA = *(const ulonglong2*)(row);       // codes k0..k0+3
            ulonglong2 eB = *(const ulonglong2*)(row + 4);   // codes k0+4..k0+7
            FMA2(dA, xp[d], eA.x, dA);
            FMA2(dB, xp[d], eA.y, dB);
            FMA2(dC, xp[d], eB.x, dC);
            FMA2(dD, xp[d], eB.y, dD);
        }
        // unpack 8 dots, dist = fl( fl(a + s_k) - 2*dot ), ascending-k compare
        unsigned int u0, u1, u2, u3, u4, u5, u6, u7;
        UNPACK2(u0, u1, dA);
        UNPACK2(u2, u3, dB);
        UNPACK2(u4, u5, dC);
        UNPACK2(u6, u7, dD);
        float4 sA = *(const float4*)(sm_s + k0);
        float4 sB = *(const float4*)(sm_s + k0 + 4);
        float dist;
        dist = __fmaf_rn(-2.0f, __uint_as_float(u0), __fadd_rn(a, sA.x));
        if (dist < best) { best = dist; bi = k0 + 0; }
        dist = __fmaf_rn(-2.0f, __uint_as_float(u1), __fadd_rn(a, sA.y));
        if (dist < best) { best = dist; bi = k0 + 1; }
        dist = __fmaf_rn(-2.0f, __uint_as_float(u2), __fadd_rn(a, sA.z));
        if (dist < best) { best = dist; bi = k0 + 2; }
        dist = __fmaf_rn(-2.0f, __uint_as_float(u3), __fadd_rn(a, sA.w));
        if (dist < best) { best = dist; bi = k0 + 3; }
        dist = __fmaf_rn(-2.0f, __uint_as_float(u4), __fadd_rn(a, sB.x));
        if (dist < best) { best = dist; bi = k0 + 4; }
        dist = __fmaf_rn(-2.0f, __uint_as_float(u5), __fadd_rn(a, sB.y));
        if (dist < best) { best = dist; bi = k0 + 5; }
        dist = __fmaf_rn(-2.0f, __uint_as_float(u6), __fadd_rn(a, sB.z));
        if (dist < best) { best = dist; bi = k0 + 6; }
        dist = __fmaf_rn(-2.0f, __uint_as_float(u7), __fadd_rn(a, sB.w));
        if (dist < best) { best = dist; bi = k0 + 7; }
    }

    // gather winning code, straight-through output, double loss accumulation
    double lacc = 0.0;
#pragma unroll
    for (int d = 0; d < VQ_D; d++) {
        unsigned int xlo, xhi;
        UNPACK2(xlo, xhi, xp[d]);
        float xd = __uint_as_float(xlo);
        float qd = smT[d * VQ_K + bi];
        float dm = __fsub_rn(qd, xd);                       // q - lat
        out[base + (long)d * VQ_HW] = __fadd_rn(xd, dm);    // lat + (q - lat)
        lacc += (double)__fmul_rn(dm, dm);
    }

#pragma unroll
    for (int off = 16; off > 0; off >>= 1)
        lacc += __shfl_down_sync(0xFFFFFFFFu, lacc, off);
    if ((threadIdx.x & 31) == 0)
        atomicAdd(&g_loss_acc, lacc);
}

// ---- finalize: vq_loss = fl( fl(m*0.25) + m ), m = mean((q-lat)^2)
__global__ void vq_finalize_kernel(float* __restrict__ out, int out_size) {
    double mean = g_loss_acc / (double)VQ_ND;
    float m = (float)mean;
    out[out_size - 1] = __fadd_rn(__fmul_rn(m, 0.25f), m);
}

extern "C" void kernel_launch(void* const* d_in, const int* in_sizes, int n_in,
                              void* d_out, int out_size) {
    const float* lat = (const float*)d_in[0];
    const float* emb = (const float*)d_in[1];
    float* out = (float*)d_out;

    static bool attr_set = false;
    if (!attr_set) {
        cudaFuncSetAttribute(vq_main_kernel,
                             cudaFuncAttributeMaxDynamicSharedMemorySize,
                             SMEM_BYTES);
        attr_set = true;
    }

    vq_setup_kernel<<<1, VQ_K>>>(emb);
    vq_main_kernel<<<VQ_NPIX / THREADS, THREADS, SMEM_BYTES>>>(lat, out);
    vq_finalize_kernel<<<1, 1>>>(out, out_size);
}